// round 9
// baseline (speedup 1.0000x reference)
#include <cuda_runtime.h>
#include <math.h>
#include <limits.h>

#define TPB 1024
#define MAXW 1024   // pad bitmaps support S <= 32768 (actual S = 4096 -> 128 words)

__device__ unsigned g_done = 0;

__device__ __forceinline__ int warp_min_i(int v) {
#pragma unroll
    for (int o = 16; o; o >>= 1) v = min(v, __shfl_down_sync(0xffffffffu, v, o));
    return v;
}
__device__ __forceinline__ int warp_or_i(int v) {
#pragma unroll
    for (int o = 16; o; o >>= 1) v |= __shfl_down_sync(0xffffffffu, v, o);
    return v;
}
__device__ __forceinline__ float warp_sum_f(float v) {
#pragma unroll
    for (int o = 16; o; o >>= 1) v += __shfl_down_sync(0xffffffffu, v, o);
    return v;
}

__global__ __launch_bounds__(TPB)
void rm_fused_kernel(const int* __restrict__ cid, const int* __restrict__ cmask,
                     const int* __restrict__ rid,
                     const float* __restrict__ ch, const float* __restrict__ rh,
                     const float* __restrict__ w, float* __restrict__ out,
                     int B, int S, int H)
{
    const int b    = blockIdx.x;
    const int t    = threadIdx.x;
    const int lane = t & 31;
    const int wid  = t >> 5;
    const int nw   = TPB >> 5;   // 32 warps

    __shared__ unsigned cbm[MAXW], rbm[MAXW];
    __shared__ int   sA[32], sB[32];
    __shared__ float fA[32], fB[32];
    __shared__ int   s_start, s_diff, s_last;

    const int words = (S + 31) >> 5;
    for (int wdi = t; wdi < words; wdi += TPB) { cbm[wdi] = 0u; rbm[wdi] = 0u; }

    const int* cidb = cid   + (size_t)b * S;
    const int* cmb  = cmask + (size_t)b * S;
    const int* ridb = rid   + (size_t)b * S;
    __syncthreads();

    // ---- single fused pass: start-of-mask, divergence, pad bitmaps ----
    int mstart = INT_MAX, diff = 0;
    const bool vec = ((S & 3) == 0) &&
        (((((unsigned long long)cidb) | ((unsigned long long)cmb) |
           ((unsigned long long)ridb)) & 15ull) == 0ull);
    if (vec) {
        const int4* c4 = (const int4*)cidb;
        const int4* m4 = (const int4*)cmb;
        const int4* r4 = (const int4*)ridb;
        const int S4 = S >> 2;
        for (int v = t; v < S4; v += TPB) {
            const int4 c = __ldg(c4 + v);
            const int4 m = __ldg(m4 + v);
            const int4 r = __ldg(r4 + v);
            const int i0 = v << 2;
            diff |= (c.x != r.x) | (c.y != r.y) | (c.z != r.z) | (c.w != r.w);
            if (m.x | m.y | m.z | m.w) {
                const int loc = m.x ? i0 : (m.y ? i0 + 1 : (m.z ? i0 + 2 : i0 + 3));
                mstart = min(mstart, loc);
            }
            const unsigned cn = (unsigned)(c.x == 0)        | ((unsigned)(c.y == 0) << 1)
                              | ((unsigned)(c.z == 0) << 2) | ((unsigned)(c.w == 0) << 3);
            const unsigned rn = (unsigned)(r.x == 0)        | ((unsigned)(r.y == 0) << 1)
                              | ((unsigned)(r.z == 0) << 2) | ((unsigned)(r.w == 0) << 3);
            if (cn) atomicOr(&cbm[i0 >> 5], cn << (i0 & 31));
            if (rn) atomicOr(&rbm[i0 >> 5], rn << (i0 & 31));
        }
    } else {
        for (int i = t; i < S; i += TPB) {
            const int c = cidb[i], m = cmb[i], r = ridb[i];
            diff |= (c != r);
            if (m) mstart = min(mstart, i);
            if (c == 0) atomicOr(&cbm[i >> 5], 1u << (i & 31));
            if (r == 0) atomicOr(&rbm[i >> 5], 1u << (i & 31));
        }
    }

    // ---- reduce mstart (min) and diff (or) ----
    mstart = warp_min_i(mstart);
    diff   = warp_or_i(diff);
    if (lane == 0) { sA[wid] = mstart; sB[wid] = diff; }
    __syncthreads();   // also publishes the bitmaps
    if (wid == 0) {
        int v = (lane < nw) ? sA[lane] : INT_MAX;
        int d = (lane < nw) ? sB[lane] : 0;
        v = warp_min_i(v); d = warp_or_i(d);
        if (lane == 0) { s_start = (v == INT_MAX) ? 0 : v; s_diff = d; }
    }
    __syncthreads();
    const int start = s_start;

    // ---- first pad >= start from bitmaps ----
    int cmin = S, rmin = S;
    const int sw = start >> 5;
    const unsigned smask = ~((1u << (start & 31)) - 1u);
    for (int wdi = sw + t; wdi < words; wdi += TPB) {
        unsigned wc = cbm[wdi], wr = rbm[wdi];
        if (wdi == sw) { wc &= smask; wr &= smask; }
        if (wc) cmin = min(cmin, (wdi << 5) + __ffs(wc) - 1);
        if (wr) rmin = min(rmin, (wdi << 5) + __ffs(wr) - 1);
    }
    cmin = warp_min_i(cmin);
    rmin = warp_min_i(rmin);
    __syncthreads();   // protect sA/sB reuse
    if (lane == 0) { sA[wid] = cmin; sB[wid] = rmin; }
    __syncthreads();
    if (t == 0) {
        int cm = S, rm = S;
        for (int i = 0; i < nw; i++) { cm = min(cm, sA[i]); rm = min(rm, sB[i]); }
        const int r_ind = s_diff ? rm : cm;          // no-div branch: r_ind = min(c_ind,S) = c_ind
        int last = min(cm, r_ind) - 1;
        if (last < 0) last += S;                     // JAX negative-index wraparound
        s_last = last;
    }
    __syncthreads();
    const int last = s_last;

    // ---- dot products at the single scored row ----
    const float* crow = ch + ((size_t)b * S + (size_t)last) * (size_t)H;
    const float* rrow = rh + ((size_t)b * S + (size_t)last) * (size_t)H;
    float cs = 0.f, rs = 0.f;
    for (int i = t; i < H; i += TPB) {
        const float wi = w[i];
        cs = fmaf(crow[i], wi, cs);
        rs = fmaf(rrow[i], wi, rs);
    }
    cs = warp_sum_f(cs);
    rs = warp_sum_f(rs);
    if (lane == 0) { fA[wid] = cs; fB[wid] = rs; }
    __syncthreads();

    if (t == 0) {
        float c = 0.f, r = 0.f;
        for (int i = 0; i < nw; i++) { c += fA[i]; r += fB[i]; }
        out[1 + b]     = c;
        out[1 + B + b] = r;
        __threadfence();
        const unsigned old = atomicAdd(&g_done, 1u);
        if (old == (unsigned)(B - 1)) {
            // last block: all scores are globally visible; compute the loss
            volatile float* vo = (volatile float*)out;
            float acc = 0.f;
            for (int i = 0; i < B; i++) {
                const float d  = vo[1 + i] - vo[1 + B + i];
                const float ls = fminf(d, 0.f) - log1pf(expf(-fabsf(d)));
                acc += -ls;
            }
            out[0] = acc / (float)B;
            atomicExch(&g_done, 0u);   // reset for next graph replay
        }
    }
}

extern "C" void kernel_launch(void* const* d_in, const int* in_sizes, int n_in,
                              void* d_out, int out_size)
{
    const int*   cid   = (const int*)d_in[0];
    const int*   cmask = (const int*)d_in[1];
    const int*   rid   = (const int*)d_in[2];
    const float* ch    = (const float*)d_in[3];
    const float* rh    = (const float*)d_in[4];
    const float* w     = (const float*)d_in[5];
    float* out = (float*)d_out;

    const int B = (out_size - 1) / 2;   // out = [loss, chosen[B], rejected[B]]
    const int S = in_sizes[0] / B;      // chosen_ids is [B,S]
    const int H = in_sizes[5];          // v_head_w is [H]

    rm_fused_kernel<<<B, TPB>>>(cid, cmask, rid, ch, rh, w, out, B, S, H);
}

// round 10
// speedup vs baseline: 1.0208x; 1.0208x over previous
#include <cuda_runtime.h>
#include <math.h>
#include <limits.h>

#define TPB 1024
#define MAXW 1024   // pad bitmaps support S <= 32768 (actual S = 4096 -> 128 words)

__device__ unsigned g_done = 0;

__device__ __forceinline__ int warp_min_i(int v) {
#pragma unroll
    for (int o = 16; o; o >>= 1) v = min(v, __shfl_down_sync(0xffffffffu, v, o));
    return v;
}
__device__ __forceinline__ int warp_or_i(int v) {
#pragma unroll
    for (int o = 16; o; o >>= 1) v |= __shfl_down_sync(0xffffffffu, v, o);
    return v;
}
__device__ __forceinline__ float warp_sum_f(float v) {
#pragma unroll
    for (int o = 16; o; o >>= 1) v += __shfl_down_sync(0xffffffffu, v, o);
    return v;
}

__global__ __launch_bounds__(TPB)
void rm_fused_kernel(const int* __restrict__ cid, const int* __restrict__ cmask,
                     const int* __restrict__ rid,
                     const float* __restrict__ ch, const float* __restrict__ rh,
                     const float* __restrict__ w, float* __restrict__ out,
                     int B, int S, int H)
{
    const int b    = blockIdx.x;
    const int t    = threadIdx.x;
    const int lane = t & 31;
    const int wid  = t >> 5;
    const int nw   = TPB >> 5;   // 32 warps

    __shared__ unsigned cbm[MAXW], rbm[MAXW];
    __shared__ int   sA[32], sB[32];
    __shared__ float fA[32], fB[32];
    __shared__ int   s_start, s_diff, s_last;

    const int words = (S + 31) >> 5;
    for (int wdi = t; wdi < words; wdi += TPB) { cbm[wdi] = 0u; rbm[wdi] = 0u; }

    const int* cidb = cid   + (size_t)b * S;
    const int* cmb  = cmask + (size_t)b * S;
    const int* ridb = rid   + (size_t)b * S;
    __syncthreads();

    // ---- single fused pass: start-of-mask, divergence, pad bitmaps ----
    int mstart = INT_MAX, diff = 0;
    const bool vec = ((S & 3) == 0) &&
        (((((unsigned long long)cidb) | ((unsigned long long)cmb) |
           ((unsigned long long)ridb)) & 15ull) == 0ull);
    if (vec) {
        const int4* c4 = (const int4*)cidb;
        const int4* m4 = (const int4*)cmb;
        const int4* r4 = (const int4*)ridb;
        const int S4 = S >> 2;
        for (int v = t; v < S4; v += TPB) {
            const int4 c = __ldg(c4 + v);
            const int4 m = __ldg(m4 + v);
            const int4 r = __ldg(r4 + v);
            const int i0 = v << 2;
            diff |= (c.x != r.x) | (c.y != r.y) | (c.z != r.z) | (c.w != r.w);
            if (m.x | m.y | m.z | m.w) {
                const int loc = m.x ? i0 : (m.y ? i0 + 1 : (m.z ? i0 + 2 : i0 + 3));
                mstart = min(mstart, loc);
            }
            const unsigned cn = (unsigned)(c.x == 0)        | ((unsigned)(c.y == 0) << 1)
                              | ((unsigned)(c.z == 0) << 2) | ((unsigned)(c.w == 0) << 3);
            const unsigned rn = (unsigned)(r.x == 0)        | ((unsigned)(r.y == 0) << 1)
                              | ((unsigned)(r.z == 0) << 2) | ((unsigned)(r.w == 0) << 3);
            if (cn) atomicOr(&cbm[i0 >> 5], cn << (i0 & 31));
            if (rn) atomicOr(&rbm[i0 >> 5], rn << (i0 & 31));
        }
    } else {
        for (int i = t; i < S; i += TPB) {
            const int c = cidb[i], m = cmb[i], r = ridb[i];
            diff |= (c != r);
            if (m) mstart = min(mstart, i);
            if (c == 0) atomicOr(&cbm[i >> 5], 1u << (i & 31));
            if (r == 0) atomicOr(&rbm[i >> 5], 1u << (i & 31));
        }
    }

    // ---- reduce mstart (min) and diff (or) ----
    mstart = warp_min_i(mstart);
    diff   = warp_or_i(diff);
    if (lane == 0) { sA[wid] = mstart; sB[wid] = diff; }
    __syncthreads();   // also publishes the bitmaps
    if (wid == 0) {
        int v = (lane < nw) ? sA[lane] : INT_MAX;
        int d = (lane < nw) ? sB[lane] : 0;
        v = warp_min_i(v); d = warp_or_i(d);
        if (lane == 0) { s_start = (v == INT_MAX) ? 0 : v; s_diff = d; }
    }
    __syncthreads();
    const int start = s_start;

    // ---- first pad >= start from bitmaps ----
    int cmin = S, rmin = S;
    const int sw = start >> 5;
    const unsigned smask = ~((1u << (start & 31)) - 1u);
    for (int wdi = sw + t; wdi < words; wdi += TPB) {
        unsigned wc = cbm[wdi], wr = rbm[wdi];
        if (wdi == sw) { wc &= smask; wr &= smask; }
        if (wc) cmin = min(cmin, (wdi << 5) + __ffs(wc) - 1);
        if (wr) rmin = min(rmin, (wdi << 5) + __ffs(wr) - 1);
    }
    cmin = warp_min_i(cmin);
    rmin = warp_min_i(rmin);
    __syncthreads();   // protect sA/sB reuse
    if (lane == 0) { sA[wid] = cmin; sB[wid] = rmin; }
    __syncthreads();
    if (t == 0) {
        int cm = S, rm = S;
        for (int i = 0; i < nw; i++) { cm = min(cm, sA[i]); rm = min(rm, sB[i]); }
        const int r_ind = s_diff ? rm : cm;          // no-div branch: r_ind = min(c_ind,S) = c_ind
        int last = min(cm, r_ind) - 1;
        if (last < 0) last += S;                     // JAX negative-index wraparound
        s_last = last;
    }
    __syncthreads();
    const int last = s_last;

    // ---- dot products at the single scored row ----
    const float* crow = ch + ((size_t)b * S + (size_t)last) * (size_t)H;
    const float* rrow = rh + ((size_t)b * S + (size_t)last) * (size_t)H;
    float cs = 0.f, rs = 0.f;
    for (int i = t; i < H; i += TPB) {
        const float wi = w[i];
        cs = fmaf(crow[i], wi, cs);
        rs = fmaf(rrow[i], wi, rs);
    }
    cs = warp_sum_f(cs);
    rs = warp_sum_f(rs);
    if (lane == 0) { fA[wid] = cs; fB[wid] = rs; }
    __syncthreads();

    if (t == 0) {
        float c = 0.f, r = 0.f;
        for (int i = 0; i < nw; i++) { c += fA[i]; r += fB[i]; }
        out[1 + b]     = c;
        out[1 + B + b] = r;
        __threadfence();
        const unsigned old = atomicAdd(&g_done, 1u);
        if (old == (unsigned)(B - 1)) {
            // last block: all scores are globally visible; compute the loss
            volatile float* vo = (volatile float*)out;
            float acc = 0.f;
            for (int i = 0; i < B; i++) {
                const float d  = vo[1 + i] - vo[1 + B + i];
                const float ls = fminf(d, 0.f) - log1pf(expf(-fabsf(d)));
                acc += -ls;
            }
            out[0] = acc / (float)B;
            atomicExch(&g_done, 0u);   // reset for next graph replay
        }
    }
}

extern "C" void kernel_launch(void* const* d_in, const int* in_sizes, int n_in,
                              void* d_out, int out_size)
{
    const int*   cid   = (const int*)d_in[0];
    const int*   cmask = (const int*)d_in[1];
    const int*   rid   = (const int*)d_in[2];
    const float* ch    = (const float*)d_in[3];
    const float* rh    = (const float*)d_in[4];
    const float* w     = (const float*)d_in[5];
    float* out = (float*)d_out;

    const int B = (out_size - 1) / 2;   // out = [loss, chosen[B], rejected[B]]
    const int S = in_sizes[0] / B;      // chosen_ids is [B,S]
    const int H = in_sizes[5];          // v_head_w is [H]

    rm_fused_kernel<<<B, TPB>>>(cid, cmask, rid, ch, rh, w, out, B, S, H);
}

// round 11
// speedup vs baseline: 1.2610x; 1.2353x over previous
#include <cuda_runtime.h>
#include <math.h>
#include <limits.h>

#define TPB 1024
#define MAXW 1024   // pad bitmaps support S <= 32768 (actual S = 4096 -> 128 words)

__device__ unsigned g_done = 0;

__device__ __forceinline__ int warp_min_i(int v) {
#pragma unroll
    for (int o = 16; o; o >>= 1) v = min(v, __shfl_down_sync(0xffffffffu, v, o));
    return v;
}
__device__ __forceinline__ int warp_or_i(int v) {
#pragma unroll
    for (int o = 16; o; o >>= 1) v |= __shfl_down_sync(0xffffffffu, v, o);
    return v;
}
__device__ __forceinline__ float warp_sum_f(float v) {
#pragma unroll
    for (int o = 16; o; o >>= 1) v += __shfl_down_sync(0xffffffffu, v, o);
    return v;
}

__global__ __launch_bounds__(TPB)
void rm_fused_kernel(const int* __restrict__ cid, const int* __restrict__ cmask,
                     const int* __restrict__ rid,
                     const float* __restrict__ ch, const float* __restrict__ rh,
                     const float* __restrict__ w, float* __restrict__ out,
                     int B, int S, int H)
{
    const int b    = blockIdx.x;
    const int t    = threadIdx.x;
    const int lane = t & 31;
    const int wid  = t >> 5;
    const int nw   = TPB >> 5;   // 32 warps

    __shared__ unsigned cbm[MAXW], rbm[MAXW];
    __shared__ int   sA[32], sB[32];
    __shared__ float fA[32], fB[32];
    __shared__ int   s_start, s_diff, s_last;

    // ---- prefetch first weight element early (overlaps the token scan) ----
    const float w0 = (t < H) ? __ldg(w + t) : 0.f;

    const int words = (S + 31) >> 5;
    for (int wdi = t; wdi < words; wdi += TPB) { cbm[wdi] = 0u; rbm[wdi] = 0u; }

    const int* cidb = cid   + (size_t)b * S;
    const int* cmb  = cmask + (size_t)b * S;
    const int* ridb = rid   + (size_t)b * S;
    __syncthreads();

    // ---- single fused pass: start-of-mask, divergence, pad bitmaps ----
    int mstart = INT_MAX, diff = 0;
    const bool vec = ((S & 3) == 0) &&
        (((((unsigned long long)cidb) | ((unsigned long long)cmb) |
           ((unsigned long long)ridb)) & 15ull) == 0ull);
    if (vec) {
        const int4* c4 = (const int4*)cidb;
        const int4* m4 = (const int4*)cmb;
        const int4* r4 = (const int4*)ridb;
        const int S4 = S >> 2;
        for (int v = t; v < S4; v += TPB) {
            const int4 c = __ldg(c4 + v);
            const int4 m = __ldg(m4 + v);
            const int4 r = __ldg(r4 + v);
            const int i0 = v << 2;
            diff |= (c.x != r.x) | (c.y != r.y) | (c.z != r.z) | (c.w != r.w);
            if (m.x | m.y | m.z | m.w) {
                const int loc = m.x ? i0 : (m.y ? i0 + 1 : (m.z ? i0 + 2 : i0 + 3));
                mstart = min(mstart, loc);
            }
            const unsigned cn = (unsigned)(c.x == 0)        | ((unsigned)(c.y == 0) << 1)
                              | ((unsigned)(c.z == 0) << 2) | ((unsigned)(c.w == 0) << 3);
            const unsigned rn = (unsigned)(r.x == 0)        | ((unsigned)(r.y == 0) << 1)
                              | ((unsigned)(r.z == 0) << 2) | ((unsigned)(r.w == 0) << 3);
            if (cn) atomicOr(&cbm[i0 >> 5], cn << (i0 & 31));
            if (rn) atomicOr(&rbm[i0 >> 5], rn << (i0 & 31));
        }
    } else {
        for (int i = t; i < S; i += TPB) {
            const int c = cidb[i], m = cmb[i], r = ridb[i];
            diff |= (c != r);
            if (m) mstart = min(mstart, i);
            if (c == 0) atomicOr(&cbm[i >> 5], 1u << (i & 31));
            if (r == 0) atomicOr(&rbm[i >> 5], 1u << (i & 31));
        }
    }

    // ---- reduce mstart (min) and diff (or) ----
    mstart = warp_min_i(mstart);
    diff   = warp_or_i(diff);
    if (lane == 0) { sA[wid] = mstart; sB[wid] = diff; }
    __syncthreads();   // also publishes the bitmaps
    if (wid == 0) {
        int v = (lane < nw) ? sA[lane] : INT_MAX;
        int d = (lane < nw) ? sB[lane] : 0;
        v = warp_min_i(v); d = warp_or_i(d);
        if (lane == 0) { s_start = (v == INT_MAX) ? 0 : v; s_diff = d; }
    }
    __syncthreads();
    const int start = s_start;

    // ---- first pad >= start from bitmaps ----
    int cmin = S, rmin = S;
    const int sw = start >> 5;
    const unsigned smask = ~((1u << (start & 31)) - 1u);
    for (int wdi = sw + t; wdi < words; wdi += TPB) {
        unsigned wc = cbm[wdi], wr = rbm[wdi];
        if (wdi == sw) { wc &= smask; wr &= smask; }
        if (wc) cmin = min(cmin, (wdi << 5) + __ffs(wc) - 1);
        if (wr) rmin = min(rmin, (wdi << 5) + __ffs(wr) - 1);
    }
    cmin = warp_min_i(cmin);
    rmin = warp_min_i(rmin);
    if (lane == 0) { sA[wid] = cmin; sB[wid] = rmin; }  // ordered vs stage-2 reads by s_start sync
    __syncthreads();
    if (wid == 0) {
        int cm = (lane < nw) ? sA[lane] : S;
        int rm = (lane < nw) ? sB[lane] : S;
        cm = warp_min_i(cm); rm = warp_min_i(rm);
        if (lane == 0) {
            const int r_ind = s_diff ? rm : cm;   // no-div branch collapses to c_ind
            int last = min(cm, r_ind) - 1;
            if (last < 0) last += S;              // JAX negative-index wraparound
            s_last = last;
        }
    }
    __syncthreads();
    const int last = s_last;

    // ---- dot products at the single scored row ----
    const float* crow = ch + ((size_t)b * S + (size_t)last) * (size_t)H;
    const float* rrow = rh + ((size_t)b * S + (size_t)last) * (size_t)H;
    float cs = 0.f, rs = 0.f;
    for (int i = t; i < H; i += TPB) {
        const float wi = (i == t) ? w0 : __ldg(w + i);
        cs = fmaf(__ldg(crow + i), wi, cs);
        rs = fmaf(__ldg(rrow + i), wi, rs);
    }
    cs = warp_sum_f(cs);
    rs = warp_sum_f(rs);
    if (lane == 0) { fA[wid] = cs; fB[wid] = rs; }
    __syncthreads();

    // ---- final reduce + score write + parallel loss tail (warp 0 only) ----
    if (wid == 0) {
        float c = (lane < nw) ? fA[lane] : 0.f;
        float r = (lane < nw) ? fB[lane] : 0.f;
        c = warp_sum_f(c);
        r = warp_sum_f(r);

        unsigned isLast = 0;
        if (lane == 0) {
            out[1 + b]     = c;
            out[1 + B + b] = r;
            __threadfence();
            isLast = (atomicAdd(&g_done, 1u) == (unsigned)(B - 1)) ? 1u : 0u;
        }
        isLast = __shfl_sync(0xffffffffu, isLast, 0);

        if (isLast) {
            // all scores globally visible (writers fenced before counter);
            // load them in parallel across lanes, bypassing L1.
            float acc = 0.f;
            for (int i = lane; i < B; i += 32) {
                const float cv = __ldcg(out + 1 + i);
                const float rv = __ldcg(out + 1 + B + i);
                const float d  = cv - rv;
                const float ls = fminf(d, 0.f) - log1pf(expf(-fabsf(d)));
                acc += -ls;
            }
            acc = warp_sum_f(acc);
            if (lane == 0) {
                out[0] = acc / (float)B;
                atomicExch(&g_done, 0u);   // reset for next graph replay
            }
        }
    }
}

extern "C" void kernel_launch(void* const* d_in, const int* in_sizes, int n_in,
                              void* d_out, int out_size)
{
    const int*   cid   = (const int*)d_in[0];
    const int*   cmask = (const int*)d_in[1];
    const int*   rid   = (const int*)d_in[2];
    const float* ch    = (const float*)d_in[3];
    const float* rh    = (const float*)d_in[4];
    const float* w     = (const float*)d_in[5];
    float* out = (float*)d_out;

    const int B = (out_size - 1) / 2;   // out = [loss, chosen[B], rejected[B]]
    const int S = in_sizes[0] / B;      // chosen_ids is [B,S]
    const int H = in_sizes[5];          // v_head_w is [H]

    rm_fused_kernel<<<B, TPB>>>(cid, cmask, rid, ch, rh, w, out, B, S, H);
}